// round 15
// baseline (speedup 1.0000x reference)
#include <cuda_runtime.h>
#include <cuda_bf16.h>
#include <cuda_fp16.h>
#include <cstdint>

#define VOCAB  32000
#define EMBED  256
#define HIDDEN 512
#define BATCH  16
#define SEQ    512
#define BT     (BATCH * SEQ)   // 8192
#define KDIM   1024            // 2*HIDDEN

typedef unsigned long long u64;

// ---------------- scratch (static device arrays) ----------------
__device__ float  g_pre[2u * BT * HIDDEN];        // [dir][bt][h]
__device__ __half gA[(size_t)BT * KDIM];          // hcat fp16 [bt][k]
__device__ __half gB[(size_t)VOCAB * KDIM];       // W_fc^T fp16 [n][k]

// ---------------- f32x2 helpers ----------------
__device__ __forceinline__ u64 fma2(u64 a, u64 b, u64 c) {
    u64 d; asm("fma.rn.f32x2 %0, %1, %2, %3;" : "=l"(d) : "l"(a), "l"(b), "l"(c)); return d;
}
__device__ __forceinline__ u64 add2(u64 a, u64 b) {
    u64 d; asm("add.rn.f32x2 %0, %1, %2;" : "=l"(d) : "l"(a), "l"(b)); return d;
}
__device__ __forceinline__ u64 dup2(float x) {
    u64 d; asm("mov.b64 %0, {%1, %1};" : "=l"(d) : "f"(x)); return d;
}
__device__ __forceinline__ float2 unp2(u64 v) {
    float2 r; asm("mov.b64 {%0, %1}, %2;" : "=f"(r.x), "=f"(r.y) : "l"(v)); return r;
}

// fast tanh: ~1e-6 rel err, MUFU-based (validated R13/R14)
__device__ __forceinline__ float ftanh(float x) {
    x = fminf(fmaxf(x, -15.f), 15.f);
    float e = __expf(2.0f * x);
    return __fdividef(e - 1.0f, e + 1.0f);
}

// ---------------- smem / cp.async helpers ----------------
__device__ __forceinline__ uint32_t smem_u32(const void* p) {
    uint32_t a;
    asm("{ .reg .u64 t; cvta.to.shared.u64 t, %1; cvt.u32.u64 %0, t; }" : "=r"(a) : "l"(p));
    return a;
}
__device__ __forceinline__ void cpa16(uint32_t dst, const void* src) {
    asm volatile("cp.async.cg.shared.global [%0], [%1], 16;" :: "r"(dst), "l"(src));
}
__device__ __forceinline__ void cpa_commit() { asm volatile("cp.async.commit_group;" ::: "memory"); }
__device__ __forceinline__ void cpa_wait1()  { asm volatile("cp.async.wait_group 1;"  ::: "memory"); }
__device__ __forceinline__ void cpa_wait0()  { asm volatile("cp.async.wait_group 0;"  ::: "memory"); }

// ---------------- cluster / DSMEM / mbarrier helpers ----------------
__device__ __forceinline__ uint32_t ctarank() {
    uint32_t r; asm("mov.u32 %0, %%cluster_ctarank;" : "=r"(r)); return r;
}
__device__ __forceinline__ void st_cluster_u64(uint32_t localAddr, uint32_t rankTo, u64 v) {
    asm volatile("{\n\t.reg .b32 ra;\n\t"
                 "mapa.shared::cluster.u32 ra, %0, %1;\n\t"
                 "st.shared::cluster.b64 [ra], %2;\n\t}"
                 :: "r"(localAddr), "r"(rankTo), "l"(v) : "memory");
}
__device__ __forceinline__ void mbar_init(uint32_t mbar, uint32_t cnt) {
    asm volatile("mbarrier.init.shared.b64 [%0], %1;" :: "r"(mbar), "r"(cnt) : "memory");
}
__device__ __forceinline__ void fence_cluster() {
    asm volatile("fence.acq_rel.cluster;" ::: "memory");
}
__device__ __forceinline__ void mbar_arrive_relaxed_cluster(uint32_t localAddr, uint32_t rankTo) {
    asm volatile("{\n\t.reg .b32 ra;\n\t"
                 "mapa.shared::cluster.u32 ra, %0, %1;\n\t"
                 "mbarrier.arrive.relaxed.cluster.shared::cluster.b64 _, [ra];\n\t}"
                 :: "r"(localAddr), "r"(rankTo) : "memory");
}
__device__ __forceinline__ void mbar_wait_acq(uint32_t mbar, uint32_t parity) {
    asm volatile(
        "{\n\t.reg .pred P;\n\t"
        "WAIT_%=:\n\t"
        "mbarrier.try_wait.parity.acquire.cluster.shared::cta.b64 P, [%0], %1;\n\t"
        "@!P bra WAIT_%=;\n\t}"
        :: "r"(mbar), "r"(parity) : "memory");
}
__device__ __forceinline__ void cluster_sync() {
    asm volatile("barrier.cluster.arrive.aligned;" ::: "memory");
    asm volatile("barrier.cluster.wait.aligned;"   ::: "memory");
}

// ---------------- mma.sync / ldmatrix ----------------
__device__ __forceinline__ void ldsm4(uint32_t* r, uint32_t addr) {
    asm volatile("ldmatrix.sync.aligned.m8n8.x4.shared.b16 {%0,%1,%2,%3}, [%4];"
                 : "=r"(r[0]), "=r"(r[1]), "=r"(r[2]), "=r"(r[3]) : "r"(addr));
}
__device__ __forceinline__ void mma_fp16(float* c, const uint32_t* a, uint32_t b0, uint32_t b1) {
    asm volatile("mma.sync.aligned.m16n8k16.row.col.f32.f16.f16.f32 "
                 "{%0,%1,%2,%3}, {%4,%5,%6,%7}, {%8,%9}, {%0,%1,%2,%3};"
                 : "+f"(c[0]), "+f"(c[1]), "+f"(c[2]), "+f"(c[3])
                 : "r"(a[0]), "r"(a[1]), "r"(a[2]), "r"(a[3]), "r"(b0), "r"(b1));
}

// ============ Kernel 1: pre = gather(emb) @ W_xh + b ============
__global__ __launch_bounds__(256) void pre_kernel(
    const int* __restrict__ inputs, const float* __restrict__ emb,
    const float* __restrict__ Wxf, const float* __restrict__ bhf,
    const float* __restrict__ Wxb, const float* __restrict__ bhb)
{
    __shared__ int   toks[64];
    __shared__ float As[32][65];
    __shared__ float Bs[32][64];

    const int tid = threadIdx.x;
    const int dir = blockIdx.y >> 3;
    const int n0  = (blockIdx.y & 7) * 64;
    const int m0  = blockIdx.x * 64;
    const float* W  = dir ? Wxb : Wxf;
    const float* bh = dir ? bhb : bhf;

    if (tid < 64) toks[tid] = inputs[m0 + tid];
    __syncthreads();

    const int ty = tid >> 4, tx = tid & 15;
    const int am = tid >> 2, akq = (tid & 3) * 4;
    const int bkr = tid >> 4, bc4 = (tid & 15) * 4;
    const size_t arow = (size_t)toks[am] * EMBED;

    float acc[4][4] = {};

    for (int k0 = 0; k0 < EMBED; k0 += 32) {
        float4 a0 = *(const float4*)&emb[arow + k0 + akq];
        float4 a1 = *(const float4*)&emb[arow + k0 + 16 + akq];
        float4 b0 = *(const float4*)&W[(size_t)(k0 + bkr) * HIDDEN + n0 + bc4];
        float4 b1 = *(const float4*)&W[(size_t)(k0 + bkr + 16) * HIDDEN + n0 + bc4];
        __syncthreads();
        As[akq + 0][am] = a0.x; As[akq + 1][am] = a0.y;
        As[akq + 2][am] = a0.z; As[akq + 3][am] = a0.w;
        As[akq + 16][am] = a1.x; As[akq + 17][am] = a1.y;
        As[akq + 18][am] = a1.z; As[akq + 19][am] = a1.w;
        *(float4*)&Bs[bkr][bc4]      = b0;
        *(float4*)&Bs[bkr + 16][bc4] = b1;
        __syncthreads();
        #pragma unroll
        for (int k = 0; k < 32; k++) {
            float4 bv = *(const float4*)&Bs[k][tx * 4];
            #pragma unroll
            for (int i = 0; i < 4; i++) {
                float a = As[k][ty * 4 + i];
                acc[i][0] += a * bv.x; acc[i][1] += a * bv.y;
                acc[i][2] += a * bv.z; acc[i][3] += a * bv.w;
            }
        }
    }

    float4 bias = *(const float4*)&bh[n0 + tx * 4];
    #pragma unroll
    for (int i = 0; i < 4; i++) {
        int row = m0 + ty * 4 + i;
        float4 o = make_float4(acc[i][0] + bias.x, acc[i][1] + bias.y,
                               acc[i][2] + bias.z, acc[i][3] + bias.w);
        *(float4*)&g_pre[((size_t)dir * BT + row) * HIDDEN + n0 + tx * 4] = o;
    }
}

// ============ Kernel 2: W_fc transpose -> fp16 [n][k] ============
__global__ __launch_bounds__(256) void convw_kernel(const float* __restrict__ W)
{
    __shared__ float s[32][33];
    const int k0 = blockIdx.x * 32;
    const int n0 = blockIdx.y * 32;
    const int tx = threadIdx.x & 31, ty = threadIdx.x >> 5;

    #pragma unroll
    for (int j = 0; j < 4; j++) {
        int ky = ty + 8 * j;
        s[ky][tx] = W[(size_t)(k0 + ky) * VOCAB + n0 + tx];
    }
    __syncthreads();
    #pragma unroll
    for (int j = 0; j < 4; j++) {
        int ny = ty + 8 * j;
        gB[(size_t)(n0 + ny) * KDIM + k0 + tx] = __float2half_rn(s[tx][ny]);
    }
}

// ============ Kernel 3: register-resident W_hh scan, elected-arrive sync ============
// 128 CTAs, cluster of 8 = (dir, batch-pair); rank = 64-wide n-slice.
// FMA: warp = k-range, lane = n-pair. Reduce: 128 threads (R12-proven).
// Per-step sync: reducers store h(s+1) slices -> __syncthreads ->
// elected thread: fence.acq_rel.cluster + 8 relaxed arrives (one per rank) ->
// all threads acquire-wait on local full[(s+1)&1] (expects 8 arrivals).
// Release-fence idiom carries all reducers' DSMEM stores.
#define NSL 64

__global__ __launch_bounds__(512, 1) __cluster_dims__(8, 1, 1)
void scan_kernel(const float* __restrict__ hprev,
                 const float* __restrict__ Whf, const float* __restrict__ Whb)
{
    __shared__ u64 hbuf[2][HIDDEN][2];   // [buf][k][batch] dup'd pairs, 16KB
    __shared__ u64 part[16][65];         // k-reduction staging (padded)
    __shared__ alignas(8) u64 fullbar[2];

    const int tid  = threadIdx.x;
    const int lane = tid & 31;           // np: n-pair within slice
    const int wkq  = tid >> 5;           // 0..15: k-range (32 k each)
    const uint32_t rank = ctarank();     // 0..7: n-slice
    const int cid  = blockIdx.x >> 3;    // 0..15
    const int dir  = cid >> 3;
    const int bg   = cid & 7;
    const int b0   = bg * 2, b1 = b0 + 1;
    const int n0   = (int)rank * NSL;
    const float* W = dir ? Whb : Whf;
    const float* preB = g_pre + (size_t)dir * BT * HIDDEN;
    const uint32_t fb = smem_u32(&fullbar[0]);

    u64 W2[32];
    {
        const int myn = n0 + 2 * lane;
        #pragma unroll
        for (int kk = 0; kk < 32; kk++)
            W2[kk] = *(const u64*)&W[(size_t)(wkq * 32 + kk) * HIDDEN + myn];
    }

    if (tid == 0) {
        mbar_init(fb,     8);   // one arrive per rank
        mbar_init(fb + 8, 8);
    }
    for (int i = tid; i < HIDDEN; i += 512) {
        hbuf[0][i][0] = dup2(hprev[b0 * HIDDEN + i]);
        hbuf[0][i][1] = dup2(hprev[b1 * HIDDEN + i]);
    }
    __syncthreads();
    cluster_sync();   // mbarriers + h0 visible cluster-wide before any traffic

    // reduction identity (tid < 128): col = output u64 column (n-pair x batch)
    const int col  = tid >> 1;            // 0..63
    const int half = tid & 1;             // which 8 partials I sum
    const int rnp  = col >> 1;
    const int rb   = col & 1;
    const int rn   = n0 + rnp * 2;
    const int rbb  = rb ? b1 : b0;
    const uint32_t hx_addr = smem_u32(&hbuf[0][rn][rb]);
    const uint32_t hy_addr = smem_u32(&hbuf[0][rn + 1][rb]);
    const uint32_t bufstride = (uint32_t)(HIDDEN * 2 * sizeof(u64));
    const uint32_t rbase = (uint32_t)(half * 4);   // my 4 ranks: 0-3 or 4-7

    int ph0 = 0, ph1 = 0;

    for (int s = 0; s < SEQ; s++) {
        const int t   = dir ? (SEQ - 1 - s) : s;
        const int cur = s & 1, nxt = cur ^ 1;

        if (s) {   // wait for all ranks' h_s slices (buffer cur)
            if (cur) { mbar_wait_acq(fb + 8, ph1); ph1 ^= 1; }
            else     { mbar_wait_acq(fb,     ph0); ph0 ^= 1; }
        }

        float2 prev2 = make_float2(0.f, 0.f);
        if (tid < 128)
            prev2 = *(const float2*)&preB[((size_t)rbb * SEQ + t) * HIDDEN + rn];

        u64 a0 = 0ull, a1 = 0ull;
        #pragma unroll
        for (int kk = 0; kk < 32; kk++) {
            ulonglong2 hv = *(const ulonglong2*)&hbuf[cur][wkq * 32 + kk][0];
            a0 = fma2(hv.x, W2[kk], a0);
            a1 = fma2(hv.y, W2[kk], a1);
        }
        part[wkq][lane * 2]     = a0;
        part[wkq][lane * 2 + 1] = a1;
        __syncthreads();

        if (tid < 128) {
            const int qb = half * 8;
            u64 acc = part[qb][col];
            #pragma unroll
            for (int q = 1; q < 8; q++) acc = add2(acc, part[qb + q][col]);
            u64 other = __shfl_xor_sync(0xffffffffu, acc, 1);
            acc = add2(acc, other);

            float2 u = unp2(acc);
            float hx = ftanh(u.x + prev2.x);
            float hy = ftanh(u.y + prev2.y);

            if (half == 0) {
                __half2 hp = __floats2half2_rn(hx, hy);
                *(uint32_t*)&gA[((size_t)rbb * SEQ + t) * KDIM + dir * HIDDEN + rn]
                    = *(uint32_t*)&hp;
            }

            if (s < SEQ - 1) {
                u64 dx = dup2(hx), dy = dup2(hy);
                uint32_t ax = hx_addr + (uint32_t)nxt * bufstride;
                uint32_t ay = hy_addr + (uint32_t)nxt * bufstride;
                #pragma unroll
                for (uint32_t rr = 0; rr < 4; rr++) {
                    st_cluster_u64(ax, rbase + rr, dx);
                    st_cluster_u64(ay, rbase + rr, dy);
                }
            }
        }

        if (s < SEQ - 1) {
            __syncthreads();   // all reducers' stores issued before the fence
            if (tid == 0) {
                fence_cluster();   // release: carries all reducers' DSMEM stores
                uint32_t barNext = fb + (uint32_t)nxt * 8;
                #pragma unroll
                for (uint32_t rr = 0; rr < 8; rr++)
                    mbar_arrive_relaxed_cluster(barNext, rr);
            }
        }
    }

    cluster_sync();   // no CTA exits while remote stores may be in flight
}

// ============ Kernel 4: FC GEMM via mma.sync fp16, BK=64, 3-stage (R14 WIN) ============
#define RSB    144
#define TILEB  (128 * RSB)      // 18432
#define STAGEB (2 * TILEB)      // 36864: [A tile][B tile]
#define FC_SMEM (3 * STAGEB)    // 110592

__device__ __forceinline__ void fc_load_stage(
    uint32_t base, int kc, int m0, int n0, int tid)
{
    const int k0 = kc * 64;
    const __half* srcA = gA + (size_t)m0 * KDIM;
    const __half* srcB = gB + (size_t)n0 * KDIM;
    #pragma unroll
    for (int j = 0; j < 4; j++) {
        int u = tid + 256 * j;
        int row = u >> 3, c = u & 7;
        cpa16(base + row * RSB + c * 16, srcA + (size_t)row * KDIM + k0 + c * 8);
    }
    #pragma unroll
    for (int j = 0; j < 4; j++) {
        int u = tid + 256 * j;
        int row = u >> 3, c = u & 7;
        cpa16(base + TILEB + row * RSB + c * 16, srcB + (size_t)row * KDIM + k0 + c * 8);
    }
    cpa_commit();
}

__global__ __launch_bounds__(256, 2) void fc_kernel(
    const float* __restrict__ bfc, float* __restrict__ out)
{
    extern __shared__ char smem[];
    const uint32_t sb = smem_u32(smem);
    const int tid = threadIdx.x, lane = tid & 31, wid = tid >> 5;
    const int mw = wid & 1, nw = wid >> 1;
    const int m0 = blockIdx.x * 128, n0 = blockIdx.y * 128;

    const int q = lane >> 3, r = lane & 7;
    const uint32_t aOff = (uint32_t)((mw * 64 + (q & 1) * 8 + r) * RSB + ((q >> 1) * 8) * 2);
    const uint32_t bOff = (uint32_t)((nw * 32 + (q >> 1) * 8 + r) * RSB + ((q & 1) * 8) * 2);

    float acc[4][4][4];
    #pragma unroll
    for (int i = 0; i < 4; i++)
        #pragma unroll
        for (int j = 0; j < 4; j++) {
            acc[i][j][0] = 0.f; acc[i][j][1] = 0.f;
            acc[i][j][2] = 0.f; acc[i][j][3] = 0.f;
        }

    fc_load_stage(sb + 0 * STAGEB, 0, m0, n0, tid);
    fc_load_stage(sb + 1 * STAGEB, 1, m0, n0, tid);

    for (int kc = 0; kc < 16; kc++) {
        if (kc < 15) cpa_wait1(); else cpa_wait0();
        __syncthreads();

        const uint32_t bb = sb + (uint32_t)(kc % 3) * STAGEB;

        #pragma unroll
        for (int j16 = 0; j16 < 4; j16++) {
            const uint32_t kb = (uint32_t)j16 * 32;
            uint32_t ah[4][4], bh[2][4];
            #pragma unroll
            for (int mf = 0; mf < 4; mf++)
                ldsm4(ah[mf], bb + aOff + mf * (16 * RSB) + kb);
            #pragma unroll
            for (int nf2 = 0; nf2 < 2; nf2++)
                ldsm4(bh[nf2], bb + TILEB + bOff + nf2 * (16 * RSB) + kb);

            #pragma unroll
            for (int mf = 0; mf < 4; mf++)
                #pragma unroll
                for (int nf2 = 0; nf2 < 2; nf2++) {
                    mma_fp16(acc[mf][nf2 * 2],     ah[mf], bh[nf2][0], bh[nf2][1]);
                    mma_fp16(acc[mf][nf2 * 2 + 1], ah[mf], bh[nf2][2], bh[nf2][3]);
                }
        }

        if (kc < 14) fc_load_stage(sb + (uint32_t)((kc + 2) % 3) * STAGEB,
                                   kc + 2, m0, n0, tid);
    }

    #pragma unroll
    for (int mf = 0; mf < 4; mf++) {
        const int row = m0 + mw * 64 + mf * 16 + (lane >> 2);
        #pragma unroll
        for (int nf = 0; nf < 4; nf++) {
            const int col = n0 + nw * 32 + nf * 8 + 2 * (lane & 3);
            const float2 bb2 = __ldg((const float2*)&bfc[col]);
            float2 v0 = make_float2(acc[mf][nf][0] + bb2.x, acc[mf][nf][1] + bb2.y);
            float2 v1 = make_float2(acc[mf][nf][2] + bb2.x, acc[mf][nf][3] + bb2.y);
            *(float2*)&out[(size_t)row * VOCAB + col]       = v0;
            *(float2*)&out[(size_t)(row + 8) * VOCAB + col] = v1;
        }
    }
}

// ============ launch ============
extern "C" void kernel_launch(void* const* d_in, const int* in_sizes, int n_in,
                              void* d_out, int out_size) {
    const int*   inputs = (const int*)  d_in[0];
    const float* h_prev = (const float*)d_in[1];
    const float* emb    = (const float*)d_in[2];
    const float* W_xh_f = (const float*)d_in[3];
    const float* W_hh_f = (const float*)d_in[4];
    const float* b_h_f  = (const float*)d_in[5];
    const float* W_xh_b = (const float*)d_in[6];
    const float* W_hh_b = (const float*)d_in[7];
    const float* b_h_b  = (const float*)d_in[8];
    const float* W_fc   = (const float*)d_in[9];
    const float* b_fc   = (const float*)d_in[10];
    float* out = (float*)d_out;

    cudaFuncSetAttribute(fc_kernel, cudaFuncAttributeMaxDynamicSharedMemorySize, FC_SMEM);

    pre_kernel<<<dim3(BT / 64, 16), 256>>>(inputs, emb, W_xh_f, b_h_f, W_xh_b, b_h_b);
    convw_kernel<<<dim3(KDIM / 32, VOCAB / 32), 256>>>(W_fc);
    scan_kernel<<<128, 512>>>(h_prev, W_hh_f, W_hh_b);
    fc_kernel<<<dim3(BT / 128, VOCAB / 128), 256, FC_SMEM>>>(b_fc, out);
}

// round 16
// speedup vs baseline: 1.0950x; 1.0950x over previous
#include <cuda_runtime.h>
#include <cuda_bf16.h>
#include <cuda_fp16.h>
#include <cstdint>

#define VOCAB  32000
#define EMBED  256
#define HIDDEN 512
#define BATCH  16
#define SEQ    512
#define BT     (BATCH * SEQ)   // 8192
#define KDIM   1024            // 2*HIDDEN

typedef unsigned long long u64;

// ---------------- scratch (static device arrays) ----------------
__device__ float  g_pre[2u * BT * HIDDEN];        // [dir][bt][h]
__device__ __half gA[(size_t)BT * KDIM];          // hcat fp16 [bt][k]
__device__ __half gB[(size_t)VOCAB * KDIM];       // W_fc^T fp16 [n][k]

// ---------------- f32x2 helpers ----------------
__device__ __forceinline__ u64 fma2(u64 a, u64 b, u64 c) {
    u64 d; asm("fma.rn.f32x2 %0, %1, %2, %3;" : "=l"(d) : "l"(a), "l"(b), "l"(c)); return d;
}
__device__ __forceinline__ u64 add2(u64 a, u64 b) {
    u64 d; asm("add.rn.f32x2 %0, %1, %2;" : "=l"(d) : "l"(a), "l"(b)); return d;
}
__device__ __forceinline__ u64 dup2(float x) {
    u64 d; asm("mov.b64 %0, {%1, %1};" : "=l"(d) : "f"(x)); return d;
}
__device__ __forceinline__ float2 unp2(u64 v) {
    float2 r; asm("mov.b64 {%0, %1}, %2;" : "=f"(r.x), "=f"(r.y) : "l"(v)); return r;
}

// fast tanh: ~1e-6 rel err, MUFU-based (validated R13/R14)
__device__ __forceinline__ float ftanh(float x) {
    x = fminf(fmaxf(x, -15.f), 15.f);
    float e = __expf(2.0f * x);
    return __fdividef(e - 1.0f, e + 1.0f);
}

// ---------------- smem / cp.async helpers ----------------
__device__ __forceinline__ uint32_t smem_u32(const void* p) {
    uint32_t a;
    asm("{ .reg .u64 t; cvta.to.shared.u64 t, %1; cvt.u32.u64 %0, t; }" : "=r"(a) : "l"(p));
    return a;
}
__device__ __forceinline__ void cpa16(uint32_t dst, const void* src) {
    asm volatile("cp.async.cg.shared.global [%0], [%1], 16;" :: "r"(dst), "l"(src));
}
__device__ __forceinline__ void cpa_commit() { asm volatile("cp.async.commit_group;" ::: "memory"); }
__device__ __forceinline__ void cpa_wait1()  { asm volatile("cp.async.wait_group 1;"  ::: "memory"); }
__device__ __forceinline__ void cpa_wait0()  { asm volatile("cp.async.wait_group 0;"  ::: "memory"); }

// ---------------- cluster / DSMEM helpers ----------------
__device__ __forceinline__ uint32_t ctarank() {
    uint32_t r; asm("mov.u32 %0, %%cluster_ctarank;" : "=r"(r)); return r;
}
__device__ __forceinline__ void st_cluster_u64(uint32_t localAddr, uint32_t rankTo, u64 v) {
    asm volatile("{\n\t.reg .b32 ra;\n\t"
                 "mapa.shared::cluster.u32 ra, %0, %1;\n\t"
                 "st.shared::cluster.b64 [ra], %2;\n\t}"
                 :: "r"(localAddr), "r"(rankTo), "l"(v) : "memory");
}
__device__ __forceinline__ void cluster_sync() {
    asm volatile("barrier.cluster.arrive.aligned;" ::: "memory");
    asm volatile("barrier.cluster.wait.aligned;"   ::: "memory");
}

// ---------------- mma.sync / ldmatrix ----------------
__device__ __forceinline__ void ldsm4(uint32_t* r, uint32_t addr) {
    asm volatile("ldmatrix.sync.aligned.m8n8.x4.shared.b16 {%0,%1,%2,%3}, [%4];"
                 : "=r"(r[0]), "=r"(r[1]), "=r"(r[2]), "=r"(r[3]) : "r"(addr));
}
__device__ __forceinline__ void mma_fp16(float* c, const uint32_t* a, uint32_t b0, uint32_t b1) {
    asm volatile("mma.sync.aligned.m16n8k16.row.col.f32.f16.f16.f32 "
                 "{%0,%1,%2,%3}, {%4,%5,%6,%7}, {%8,%9}, {%0,%1,%2,%3};"
                 : "+f"(c[0]), "+f"(c[1]), "+f"(c[2]), "+f"(c[3])
                 : "r"(a[0]), "r"(a[1]), "r"(a[2]), "r"(a[3]), "r"(b0), "r"(b1));
}

// ============ Kernel 1: pre = gather(emb) @ W_xh + b ============
__global__ __launch_bounds__(256) void pre_kernel(
    const int* __restrict__ inputs, const float* __restrict__ emb,
    const float* __restrict__ Wxf, const float* __restrict__ bhf,
    const float* __restrict__ Wxb, const float* __restrict__ bhb)
{
    __shared__ int   toks[64];
    __shared__ float As[32][65];
    __shared__ float Bs[32][64];

    const int tid = threadIdx.x;
    const int dir = blockIdx.y >> 3;
    const int n0  = (blockIdx.y & 7) * 64;
    const int m0  = blockIdx.x * 64;
    const float* W  = dir ? Wxb : Wxf;
    const float* bh = dir ? bhb : bhf;

    if (tid < 64) toks[tid] = inputs[m0 + tid];
    __syncthreads();

    const int ty = tid >> 4, tx = tid & 15;
    const int am = tid >> 2, akq = (tid & 3) * 4;
    const int bkr = tid >> 4, bc4 = (tid & 15) * 4;
    const size_t arow = (size_t)toks[am] * EMBED;

    float acc[4][4] = {};

    for (int k0 = 0; k0 < EMBED; k0 += 32) {
        float4 a0 = *(const float4*)&emb[arow + k0 + akq];
        float4 a1 = *(const float4*)&emb[arow + k0 + 16 + akq];
        float4 b0 = *(const float4*)&W[(size_t)(k0 + bkr) * HIDDEN + n0 + bc4];
        float4 b1 = *(const float4*)&W[(size_t)(k0 + bkr + 16) * HIDDEN + n0 + bc4];
        __syncthreads();
        As[akq + 0][am] = a0.x; As[akq + 1][am] = a0.y;
        As[akq + 2][am] = a0.z; As[akq + 3][am] = a0.w;
        As[akq + 16][am] = a1.x; As[akq + 17][am] = a1.y;
        As[akq + 18][am] = a1.z; As[akq + 19][am] = a1.w;
        *(float4*)&Bs[bkr][bc4]      = b0;
        *(float4*)&Bs[bkr + 16][bc4] = b1;
        __syncthreads();
        #pragma unroll
        for (int k = 0; k < 32; k++) {
            float4 bv = *(const float4*)&Bs[k][tx * 4];
            #pragma unroll
            for (int i = 0; i < 4; i++) {
                float a = As[k][ty * 4 + i];
                acc[i][0] += a * bv.x; acc[i][1] += a * bv.y;
                acc[i][2] += a * bv.z; acc[i][3] += a * bv.w;
            }
        }
    }

    float4 bias = *(const float4*)&bh[n0 + tx * 4];
    #pragma unroll
    for (int i = 0; i < 4; i++) {
        int row = m0 + ty * 4 + i;
        float4 o = make_float4(acc[i][0] + bias.x, acc[i][1] + bias.y,
                               acc[i][2] + bias.z, acc[i][3] + bias.w);
        *(float4*)&g_pre[((size_t)dir * BT + row) * HIDDEN + n0 + tx * 4] = o;
    }
}

// ============ Kernel 2: scan (clusters 0-15) + convw (clusters 16-19) ============
// Scan: R14-proven register-resident W_hh scan, cluster_sync per step.
// Convw clusters run on otherwise-idle SMs, fully hidden under the scan.
#define NSL 64

__device__ void convw_role(const float* __restrict__ W, int cid2, int tid,
                           float* s /* [32][65] scratch */)
{
    // 16000 tiles of 32k x 64n; 32 CTAs, stride 32.
    for (int tix = cid2; tix < 16000; tix += 32) {
        const int kt = tix & 31;          // k-tile
        const int nt = tix >> 5;          // n-tile
        const int k0 = kt * 32;
        const int n0 = nt * 64;

        {   // load 32 rows x 64 cols, one float4 per thread (coalesced)
            const int row = tid >> 4;           // 0..31
            const int c4  = (tid & 15) * 4;     // 0..60
            float4 v = *(const float4*)&W[(size_t)(k0 + row) * VOCAB + n0 + c4];
            s[row * 65 + c4 + 0] = v.x; s[row * 65 + c4 + 1] = v.y;
            s[row * 65 + c4 + 2] = v.z; s[row * 65 + c4 + 3] = v.w;
        }
        __syncthreads();
        {   // store transposed: 64 n-rows x 32 k, 4 k per thread (conflict-free)
            const int n    = tid >> 3;          // 0..63
            const int kseg = (tid & 7) * 4;     // 0..28
            float f0 = s[(kseg + 0) * 65 + n];
            float f1 = s[(kseg + 1) * 65 + n];
            float f2 = s[(kseg + 2) * 65 + n];
            float f3 = s[(kseg + 3) * 65 + n];
            __half2 p0 = __floats2half2_rn(f0, f1);
            __half2 p1 = __floats2half2_rn(f2, f3);
            *(uint2*)&gB[(size_t)(n0 + n) * KDIM + k0 + kseg]
                = make_uint2(*(uint32_t*)&p0, *(uint32_t*)&p1);
        }
        __syncthreads();
    }
}

__global__ __launch_bounds__(512, 1) __cluster_dims__(8, 1, 1)
void scan_kernel(const float* __restrict__ hprev,
                 const float* __restrict__ Whf, const float* __restrict__ Whb,
                 const float* __restrict__ Wfc)
{
    __shared__ u64 hbuf[2][HIDDEN][2];   // [buf][k][batch] dup'd pairs, 16KB
    __shared__ u64 part[16][65];         // k-reduction staging (padded)

    const int tid = threadIdx.x;

    if (blockIdx.x >= 128) {   // convw role (clusters 16-19)
        convw_role(Wfc, (int)blockIdx.x - 128, tid, (float*)hbuf);
        return;
    }

    const int lane = tid & 31;           // np: n-pair within slice
    const int wkq  = tid >> 5;           // 0..15: k-range (32 k each)
    const uint32_t rank = ctarank();     // 0..7: n-slice
    const int cid  = blockIdx.x >> 3;    // 0..15
    const int dir  = cid >> 3;
    const int bg   = cid & 7;
    const int b0   = bg * 2, b1 = b0 + 1;
    const int n0   = (int)rank * NSL;
    const float* W = dir ? Whb : Whf;
    const float* preB = g_pre + (size_t)dir * BT * HIDDEN;

    u64 W2[32];
    {
        const int myn = n0 + 2 * lane;
        #pragma unroll
        for (int kk = 0; kk < 32; kk++)
            W2[kk] = *(const u64*)&W[(size_t)(wkq * 32 + kk) * HIDDEN + myn];
    }

    for (int i = tid; i < HIDDEN; i += 512) {
        hbuf[0][i][0] = dup2(hprev[b0 * HIDDEN + i]);
        hbuf[0][i][1] = dup2(hprev[b1 * HIDDEN + i]);
    }
    __syncthreads();
    cluster_sync();

    // reduction identity (tid < 128): col = output u64 column (n-pair x batch)
    const int col  = tid >> 1;            // 0..63
    const int half = tid & 1;             // which 8 partials I sum
    const int rnp  = col >> 1;
    const int rb   = col & 1;
    const int rn   = n0 + rnp * 2;
    const int rbb  = rb ? b1 : b0;
    const uint32_t hx_addr = smem_u32(&hbuf[0][rn][rb]);
    const uint32_t hy_addr = smem_u32(&hbuf[0][rn + 1][rb]);
    const uint32_t bufstride = (uint32_t)(HIDDEN * 2 * sizeof(u64));
    const uint32_t rbase = (uint32_t)(half * 4);   // my 4 ranks: 0-3 or 4-7

    for (int s = 0; s < SEQ; s++) {
        const int t   = dir ? (SEQ - 1 - s) : s;
        const int cur = s & 1, nxt = cur ^ 1;

        float2 prev2 = make_float2(0.f, 0.f);
        if (tid < 128)
            prev2 = *(const float2*)&preB[((size_t)rbb * SEQ + t) * HIDDEN + rn];

        u64 a0 = 0ull, a1 = 0ull;
        #pragma unroll
        for (int kk = 0; kk < 32; kk++) {
            ulonglong2 hv = *(const ulonglong2*)&hbuf[cur][wkq * 32 + kk][0];
            a0 = fma2(hv.x, W2[kk], a0);
            a1 = fma2(hv.y, W2[kk], a1);
        }
        part[wkq][lane * 2]     = a0;
        part[wkq][lane * 2 + 1] = a1;
        __syncthreads();

        if (tid < 128) {
            const int qb = half * 8;
            u64 acc = part[qb][col];
            #pragma unroll
            for (int q = 1; q < 8; q++) acc = add2(acc, part[qb + q][col]);
            u64 other = __shfl_xor_sync(0xffffffffu, acc, 1);
            acc = add2(acc, other);

            float2 u = unp2(acc);
            float hx = ftanh(u.x + prev2.x);
            float hy = ftanh(u.y + prev2.y);

            if (half == 0) {
                __half2 hp = __floats2half2_rn(hx, hy);
                *(uint32_t*)&gA[((size_t)rbb * SEQ + t) * KDIM + dir * HIDDEN + rn]
                    = *(uint32_t*)&hp;
            }

            u64 dx = dup2(hx), dy = dup2(hy);
            uint32_t ax = hx_addr + (uint32_t)nxt * bufstride;
            uint32_t ay = hy_addr + (uint32_t)nxt * bufstride;
            #pragma unroll
            for (uint32_t rr = 0; rr < 4; rr++) {
                st_cluster_u64(ax, rbase + rr, dx);
                st_cluster_u64(ay, rbase + rr, dy);
            }
        }
        cluster_sync();
    }
}

// ============ Kernel 3: FC GEMM via mma.sync fp16, BK=64, 3-stage (R14 WIN) ============
#define RSB    144
#define TILEB  (128 * RSB)      // 18432
#define STAGEB (2 * TILEB)      // 36864: [A tile][B tile]
#define FC_SMEM (3 * STAGEB)    // 110592

__device__ __forceinline__ void fc_load_stage(
    uint32_t base, int kc, int m0, int n0, int tid)
{
    const int k0 = kc * 64;
    const __half* srcA = gA + (size_t)m0 * KDIM;
    const __half* srcB = gB + (size_t)n0 * KDIM;
    #pragma unroll
    for (int j = 0; j < 4; j++) {
        int u = tid + 256 * j;
        int row = u >> 3, c = u & 7;
        cpa16(base + row * RSB + c * 16, srcA + (size_t)row * KDIM + k0 + c * 8);
    }
    #pragma unroll
    for (int j = 0; j < 4; j++) {
        int u = tid + 256 * j;
        int row = u >> 3, c = u & 7;
        cpa16(base + TILEB + row * RSB + c * 16, srcB + (size_t)row * KDIM + k0 + c * 8);
    }
    cpa_commit();
}

__global__ __launch_bounds__(256, 2) void fc_kernel(
    const float* __restrict__ bfc, float* __restrict__ out)
{
    extern __shared__ char smem[];
    const uint32_t sb = smem_u32(smem);
    const int tid = threadIdx.x, lane = tid & 31, wid = tid >> 5;
    const int mw = wid & 1, nw = wid >> 1;
    const int m0 = blockIdx.x * 128, n0 = blockIdx.y * 128;

    const int q = lane >> 3, r = lane & 7;
    const uint32_t aOff = (uint32_t)((mw * 64 + (q & 1) * 8 + r) * RSB + ((q >> 1) * 8) * 2);
    const uint32_t bOff = (uint32_t)((nw * 32 + (q >> 1) * 8 + r) * RSB + ((q & 1) * 8) * 2);

    float acc[4][4][4];
    #pragma unroll
    for (int i = 0; i < 4; i++)
        #pragma unroll
        for (int j = 0; j < 4; j++) {
            acc[i][j][0] = 0.f; acc[i][j][1] = 0.f;
            acc[i][j][2] = 0.f; acc[i][j][3] = 0.f;
        }

    fc_load_stage(sb + 0 * STAGEB, 0, m0, n0, tid);
    fc_load_stage(sb + 1 * STAGEB, 1, m0, n0, tid);

    for (int kc = 0; kc < 16; kc++) {
        if (kc < 15) cpa_wait1(); else cpa_wait0();
        __syncthreads();

        const uint32_t bb = sb + (uint32_t)(kc % 3) * STAGEB;

        #pragma unroll
        for (int j16 = 0; j16 < 4; j16++) {
            const uint32_t kb = (uint32_t)j16 * 32;
            uint32_t ah[4][4], bh[2][4];
            #pragma unroll
            for (int mf = 0; mf < 4; mf++)
                ldsm4(ah[mf], bb + aOff + mf * (16 * RSB) + kb);
            #pragma unroll
            for (int nf2 = 0; nf2 < 2; nf2++)
                ldsm4(bh[nf2], bb + TILEB + bOff + nf2 * (16 * RSB) + kb);

            #pragma unroll
            for (int mf = 0; mf < 4; mf++)
                #pragma unroll
                for (int nf2 = 0; nf2 < 2; nf2++) {
                    mma_fp16(acc[mf][nf2 * 2],     ah[mf], bh[nf2][0], bh[nf2][1]);
                    mma_fp16(acc[mf][nf2 * 2 + 1], ah[mf], bh[nf2][2], bh[nf2][3]);
                }
        }

        if (kc < 14) fc_load_stage(sb + (uint32_t)((kc + 2) % 3) * STAGEB,
                                   kc + 2, m0, n0, tid);
    }

    #pragma unroll
    for (int mf = 0; mf < 4; mf++) {
        const int row = m0 + mw * 64 + mf * 16 + (lane >> 2);
        #pragma unroll
        for (int nf = 0; nf < 4; nf++) {
            const int col = n0 + nw * 32 + nf * 8 + 2 * (lane & 3);
            const float2 bb2 = __ldg((const float2*)&bfc[col]);
            float2 v0 = make_float2(acc[mf][nf][0] + bb2.x, acc[mf][nf][1] + bb2.y);
            float2 v1 = make_float2(acc[mf][nf][2] + bb2.x, acc[mf][nf][3] + bb2.y);
            *(float2*)&out[(size_t)row * VOCAB + col]       = v0;
            *(float2*)&out[(size_t)(row + 8) * VOCAB + col] = v1;
        }
    }
}

// ============ launch ============
extern "C" void kernel_launch(void* const* d_in, const int* in_sizes, int n_in,
                              void* d_out, int out_size) {
    const int*   inputs = (const int*)  d_in[0];
    const float* h_prev = (const float*)d_in[1];
    const float* emb    = (const float*)d_in[2];
    const float* W_xh_f = (const float*)d_in[3];
    const float* W_hh_f = (const float*)d_in[4];
    const float* b_h_f  = (const float*)d_in[5];
    const float* W_xh_b = (const float*)d_in[6];
    const float* W_hh_b = (const float*)d_in[7];
    const float* b_h_b  = (const float*)d_in[8];
    const float* W_fc   = (const float*)d_in[9];
    const float* b_fc   = (const float*)d_in[10];
    float* out = (float*)d_out;

    cudaFuncSetAttribute(fc_kernel, cudaFuncAttributeMaxDynamicSharedMemorySize, FC_SMEM);

    pre_kernel<<<dim3(BT / 64, 16), 256>>>(inputs, emb, W_xh_f, b_h_f, W_xh_b, b_h_b);
    scan_kernel<<<160, 512>>>(h_prev, W_hh_f, W_hh_b, W_fc);
    fc_kernel<<<dim3(BT / 128, VOCAB / 128), 256, FC_SMEM>>>(b_fc, out);
}